// round 5
// baseline (speedup 1.0000x reference)
#include <cuda_runtime.h>

#define NF  256
#define GS  16
#define NG  16
#define HWS 3136        // 56*56
#define MB  32
#define NTOT (MB*HWS)   // 100352
#define NPAIR 136       // 16*17/2
#define NF2  (HWS/2)    // 1568 float2 positions

typedef unsigned long long u64;

// Scratch (device globals: no allocation allowed)
__device__ float g_part[NG][MB][152]; // per (g,m) block: 136 gram pairs + 16 channel sums
__device__ float g_W[NG][NPAIR];      // lower-tri inv(chol(Sigma)), k = i*(i+1)/2 + j
__device__ float g_b[NG][GS];         // b_i = sum_{j<=i} W_ij * mu_j

// ---------------------------------------------------------------------------
// packed f32x2 helpers
// ---------------------------------------------------------------------------
__device__ __forceinline__ u64 ffma2(u64 a, u64 b, u64 c) {
    u64 d;
    asm("fma.rn.f32x2 %0, %1, %2, %3;" : "=l"(d) : "l"(a), "l"(b), "l"(c));
    return d;
}
__device__ __forceinline__ float2 u2f2(u64 v) {
    float2 f;
    asm("mov.b64 {%0, %1}, %2;" : "=f"(f.x), "=f"(f.y) : "l"(v));
    return f;
}
__device__ __forceinline__ u64 splat2(float v) {
    u64 d;
    asm("mov.b64 %0, {%1, %1};" : "=l"(d) : "f"(v));
    return d;
}

// ---------------------------------------------------------------------------
// Kernel 1: per-group raw Gram + channel sums, quarter-block decomposition.
// Grid (g=16, m=32), 320 threads = 10 warps. Warp w owns quarter-block
// (QI,QJ): 4x4 channel tile => 16 accs (10 if diagonal). ~60 regs/thread
// -> 3 blocks/SM residency (~94% warp occ). Diagonal warps also do the
// channel sums for their 4 channels.
// ---------------------------------------------------------------------------
template<int QI, int QJ>
__device__ __forceinline__ void qb_warp(const float* __restrict__ base,
                                        int lane, float* __restrict__ part) {
    constexpr bool DIAG = (QI == QJ);
    constexpr int NACC = DIAG ? 10 : 16;

    u64 acc[NACC];
#pragma unroll
    for (int k = 0; k < NACC; k++) acc[k] = 0ull;
    float s[4];
#pragma unroll
    for (int c = 0; c < 4; c++) s[c] = 0.f;

    for (int f = lane; f < NF2; f += 32) {     // 49 iterations
        u64 va[4];
#pragma unroll
        for (int a = 0; a < 4; a++)
            va[a] = ((const u64*)(base + (size_t)(4 * QI + a) * HWS))[f];
        if (DIAG) {
            int k = 0;
#pragma unroll
            for (int a = 0; a < 4; a++) {
#pragma unroll
                for (int b = 0; b <= a; b++) { acc[k] = ffma2(va[a], va[b], acc[k]); k++; }
                float2 t = u2f2(va[a]);
                s[a] += t.x + t.y;
            }
        } else {
            u64 vb[4];
#pragma unroll
            for (int b = 0; b < 4; b++)
                vb[b] = ((const u64*)(base + (size_t)(4 * QJ + b) * HWS))[f];
#pragma unroll
            for (int a = 0; a < 4; a++)
#pragma unroll
                for (int b = 0; b < 4; b++)
                    acc[a * 4 + b] = ffma2(va[a], vb[b], acc[a * 4 + b]);
        }
    }

    // reduce + write disjoint partial entries
    const int DA[10] = {0,1,1,2,2,2,3,3,3,3};
    const int DB[10] = {0,0,1,0,1,2,0,1,2,3};
#pragma unroll
    for (int t = 0; t < NACC; t++) {
        float2 p = u2f2(acc[t]);
        float v = p.x + p.y;
#pragma unroll
        for (int sh = 16; sh > 0; sh >>= 1)
            v += __shfl_xor_sync(0xFFFFFFFFu, v, sh);
        if (lane == 0) {
            const int a = DIAG ? DA[t] : (t >> 2);
            const int b = DIAG ? DB[t] : (t & 3);
            const int i = 4 * QI + a;
            const int j = 4 * QJ + b;
            part[i * (i + 1) / 2 + j] = v;
        }
    }
    if (DIAG) {
#pragma unroll
        for (int c = 0; c < 4; c++) {
            float v = s[c];
#pragma unroll
            for (int sh = 16; sh > 0; sh >>= 1)
                v += __shfl_xor_sync(0xFFFFFFFFu, v, sh);
            if (lane == 0) part[136 + 4 * QI + c] = v;
        }
    }
}

__global__ __launch_bounds__(320, 3) void stats_kernel(const float* __restrict__ x) {
    const int g = blockIdx.x;
    const int m = blockIdx.y;
    const float* base = x + ((size_t)m * NF + (size_t)g * GS) * HWS;
    const int wid  = threadIdx.x >> 5;
    const int lane = threadIdx.x & 31;
    float* part = g_part[g][m];
    switch (wid) {
        case 0: qb_warp<0,0>(base, lane, part); break;
        case 1: qb_warp<1,0>(base, lane, part); break;
        case 2: qb_warp<1,1>(base, lane, part); break;
        case 3: qb_warp<2,0>(base, lane, part); break;
        case 4: qb_warp<2,1>(base, lane, part); break;
        case 5: qb_warp<2,2>(base, lane, part); break;
        case 6: qb_warp<3,0>(base, lane, part); break;
        case 7: qb_warp<3,1>(base, lane, part); break;
        case 8: qb_warp<3,2>(base, lane, part); break;
        case 9: qb_warp<3,3>(base, lane, part); break;
    }
}

// ---------------------------------------------------------------------------
// Kernel 2: reduce partials -> sigma -> Cholesky -> inverse -> (W, b).
// One warp per group (512 threads), fp32 throughout.
// ---------------------------------------------------------------------------
__global__ __launch_bounds__(512) void solve_kernel() {
    __shared__ float a [NG][GS][GS + 1];
    __shared__ float w [NG][GS][GS + 1];
    __shared__ float mu[NG][GS];
    __shared__ float red[NG][152];

    const int g    = threadIdx.x >> 5;
    const int lane = threadIdx.x & 31;
    const float n = (float)NTOT;

    for (int e = lane; e < 152; e += 32) {
        float s0 = 0.f, s1 = 0.f, s2 = 0.f, s3 = 0.f;
        for (int c = 0; c < MB; c += 4) {
            s0 += g_part[g][c + 0][e];
            s1 += g_part[g][c + 1][e];
            s2 += g_part[g][c + 2][e];
            s3 += g_part[g][c + 3][e];
        }
        red[g][e] = (s0 + s1) + (s2 + s3);
    }
    __syncwarp();

    if (lane < GS) mu[g][lane] = red[g][136 + lane] / n;
    __syncwarp();

    for (int idx = lane; idx < 256; idx += 32) {
        const int i = idx >> 4, j = idx & 15;
        const int ii = i > j ? i : j;
        const int jj = i > j ? j : i;
        float G = red[g][ii * (ii + 1) / 2 + jj];
        float sh = (G - n * mu[g][i] * mu[g][j]) / (n - 1.0f);
        a[g][i][j] = (1.0f - 1e-6f) * sh + ((i == j) ? 1e-6f : 0.0f);
    }
    __syncwarp();

    // Cholesky in-place (lower), lane i owns row i
    for (int j = 0; j < GS; j++) {
        if (lane == j) a[g][j][j] = sqrtf(a[g][j][j]);
        __syncwarp();
        const float tjj = a[g][j][j];
        if (lane > j && lane < GS) a[g][lane][j] /= tjj;
        __syncwarp();
        if (lane > j && lane < GS) {
            const float lij = a[g][lane][j];
            for (int k = j + 1; k <= lane; k++)
                a[g][lane][k] -= lij * a[g][k][j];
        }
        __syncwarp();
    }

    // W = T^{-1}: lane j computes column j by forward substitution
    if (lane < GS) {
        const int j = lane;
        w[g][j][j] = 1.0f / a[g][j][j];
        for (int i = j + 1; i < GS; i++) {
            float s = 0.f;
            for (int k = j; k < i; k++) s += a[g][i][k] * w[g][k][j];
            w[g][i][j] = -s / a[g][i][i];
        }
        for (int i = j; i < GS; i++)
            g_W[g][i * (i + 1) / 2 + j] = w[g][i][j];
    }
    __syncwarp();

    if (lane < GS) {
        const int i = lane;
        float b = 0.f;
        for (int j = 0; j <= i; j++) b += w[g][i][j] * mu[g][j];
        g_b[g][i] = b;
    }
}

// ---------------------------------------------------------------------------
// Kernel 3: y = W*x - b (triangular), float2 payload + packed ffma2.
// v[16] as u64 (32 regs) -> ~55 regs/thread -> launch_bounds(256,4) = 32
// warps/SM. Weights/biases splatted to u64 in smem; LDS.64 broadcast per use.
// ---------------------------------------------------------------------------
__global__ __launch_bounds__(256, 4) void whiten_kernel(const float* __restrict__ x,
                                                        float* __restrict__ out) {
    const int g = blockIdx.x;
    const int m = blockIdx.y;

    __shared__ u64 sW2[NPAIR];
    __shared__ u64 snb2[GS];        // -b splat
    for (int i = threadIdx.x; i < NPAIR + GS; i += 256) {
        if (i < NPAIR) sW2[i] = splat2(g_W[g][i]);
        else           snb2[i - NPAIR] = splat2(-g_b[g][i - NPAIR]);
    }
    __syncthreads();

    const size_t base = ((size_t)m * NF + (size_t)g * GS) * HWS;

    for (int f = threadIdx.x; f < NF2; f += 256) {
        u64 v[GS];
#pragma unroll
        for (int c = 0; c < GS; c++)
            v[c] = ((const u64*)(x + base + (size_t)c * HWS))[f];

#pragma unroll
        for (int i = 0; i < GS; i++) {
            u64 y = snb2[i];
#pragma unroll
            for (int j = 0; j <= i; j++)
                y = ffma2(sW2[i * (i + 1) / 2 + j], v[j], y);
            ((u64*)(out + base + (size_t)i * HWS))[f] = y;
        }
    }
}

// ---------------------------------------------------------------------------
extern "C" void kernel_launch(void* const* d_in, const int* in_sizes, int n_in,
                              void* d_out, int out_size) {
    const float* x = (const float*)d_in[0];
    float* out = (float*)d_out;

    dim3 grid(NG, MB);
    stats_kernel<<<grid, 320>>>(x);
    solve_kernel<<<1, 512>>>();
    whiten_kernel<<<grid, 256>>>(x, out);
}

// round 6
// speedup vs baseline: 1.6227x; 1.6227x over previous
#include <cuda_runtime.h>

#define NF  256
#define GS  16
#define NG  16
#define HWS 3136        // 56*56
#define MB  32
#define NTOT (MB*HWS)   // 100352
#define NPAIR 136       // 16*17/2
#define NF2  (HWS/2)    // 1568 float2 positions
#define NF4  (HWS/4)    // 784  float4 positions
#define SS   4          // spatial split for stats (wave smoothing)
#define CH2  (NF2/SS)   // 392 float2 positions per stats chunk
#define NPART (MB*SS)   // 128 partial sets per group

typedef unsigned long long u64;

// Scratch. Layout [g][entry][chunk] so solve reduces with coalesced float4.
__device__ float g_part[NG][152][NPART];
__device__ float g_W[NG][NPAIR];      // lower-tri inv(chol(Sigma)), k = i*(i+1)/2 + j
__device__ float g_b[NG][GS];         // b_i = sum_{j<=i} W_ij * mu_j

// ---------------------------------------------------------------------------
// packed f32x2 helpers
// ---------------------------------------------------------------------------
__device__ __forceinline__ u64 ffma2(u64 a, u64 b, u64 c) {
    u64 d;
    asm("fma.rn.f32x2 %0, %1, %2, %3;" : "=l"(d) : "l"(a), "l"(b), "l"(c));
    return d;
}
__device__ __forceinline__ float2 u2f2(u64 v) {
    float2 f;
    asm("mov.b64 {%0, %1}, %2;" : "=f"(f.x), "=f"(f.y) : "l"(v));
    return f;
}

// ---------------------------------------------------------------------------
// Kernel 1: per-group raw Gram + channel sums, quarter-block decomposition,
// z-split over 4 spatial chunks. Grid (g=16, m=32, z=4), 320 threads =
// 10 warps. Warp w owns quarter-block (QI,QJ): <=16 packed accs, ~62 regs
// -> 3 blocks/SM resident; 2048 blocks ~ 4.6 waves (tail slack ~9%).
// ---------------------------------------------------------------------------
template<int QI, int QJ>
__device__ __forceinline__ void qb_warp(const float* __restrict__ base,
                                        int lane, int f0,
                                        float* __restrict__ part) {
    constexpr bool DIAG = (QI == QJ);
    constexpr int NACC = DIAG ? 10 : 16;

    u64 acc[NACC];
#pragma unroll
    for (int k = 0; k < NACC; k++) acc[k] = 0ull;
    float s[4];
#pragma unroll
    for (int c = 0; c < 4; c++) s[c] = 0.f;

    const int f1 = f0 + CH2;
    for (int f = f0 + lane; f < f1; f += 32) {   // ~12.25 iterations
        u64 va[4];
#pragma unroll
        for (int a = 0; a < 4; a++)
            va[a] = ((const u64*)(base + (size_t)(4 * QI + a) * HWS))[f];
        if (DIAG) {
            int k = 0;
#pragma unroll
            for (int a = 0; a < 4; a++) {
#pragma unroll
                for (int b = 0; b <= a; b++) { acc[k] = ffma2(va[a], va[b], acc[k]); k++; }
                float2 t = u2f2(va[a]);
                s[a] += t.x + t.y;
            }
        } else {
            u64 vb[4];
#pragma unroll
            for (int b = 0; b < 4; b++)
                vb[b] = ((const u64*)(base + (size_t)(4 * QJ + b) * HWS))[f];
#pragma unroll
            for (int a = 0; a < 4; a++)
#pragma unroll
                for (int b = 0; b < 4; b++)
                    acc[a * 4 + b] = ffma2(va[a], vb[b], acc[a * 4 + b]);
        }
    }

    // reduce + write disjoint partial entries (entry stride NPART in g_part)
    const int DA[10] = {0,1,1,2,2,2,3,3,3,3};
    const int DB[10] = {0,0,1,0,1,2,0,1,2,3};
#pragma unroll
    for (int t = 0; t < NACC; t++) {
        float2 p = u2f2(acc[t]);
        float v = p.x + p.y;
#pragma unroll
        for (int sh = 16; sh > 0; sh >>= 1)
            v += __shfl_xor_sync(0xFFFFFFFFu, v, sh);
        if (lane == 0) {
            const int a = DIAG ? DA[t] : (t >> 2);
            const int b = DIAG ? DB[t] : (t & 3);
            const int i = 4 * QI + a;
            const int j = 4 * QJ + b;
            part[(i * (i + 1) / 2 + j) * NPART] = v;
        }
    }
    if (DIAG) {
#pragma unroll
        for (int c = 0; c < 4; c++) {
            float v = s[c];
#pragma unroll
            for (int sh = 16; sh > 0; sh >>= 1)
                v += __shfl_xor_sync(0xFFFFFFFFu, v, sh);
            if (lane == 0) part[(136 + 4 * QI + c) * NPART] = v;
        }
    }
}

__global__ __launch_bounds__(320, 3) void stats_kernel(const float* __restrict__ x) {
    const int g = blockIdx.x;
    const int m = blockIdx.y;
    const int z = blockIdx.z;
    const float* base = x + ((size_t)m * NF + (size_t)g * GS) * HWS;
    const int wid  = threadIdx.x >> 5;
    const int lane = threadIdx.x & 31;
    const int f0 = z * CH2;
    float* part = &g_part[g][0][m * SS + z];
    switch (wid) {
        case 0: qb_warp<0,0>(base, lane, f0, part); break;
        case 1: qb_warp<1,0>(base, lane, f0, part); break;
        case 2: qb_warp<1,1>(base, lane, f0, part); break;
        case 3: qb_warp<2,0>(base, lane, f0, part); break;
        case 4: qb_warp<2,1>(base, lane, f0, part); break;
        case 5: qb_warp<2,2>(base, lane, f0, part); break;
        case 6: qb_warp<3,0>(base, lane, f0, part); break;
        case 7: qb_warp<3,1>(base, lane, f0, part); break;
        case 8: qb_warp<3,2>(base, lane, f0, part); break;
        case 9: qb_warp<3,3>(base, lane, f0, part); break;
    }
}

// ---------------------------------------------------------------------------
// Kernel 2: reduce partials (coalesced float4) -> sigma -> Cholesky ->
// inverse -> (W, b). One warp per group (512 threads), fp32 throughout.
// ---------------------------------------------------------------------------
__global__ __launch_bounds__(512) void solve_kernel() {
    __shared__ float a [NG][GS][GS + 1];
    __shared__ float w [NG][GS][GS + 1];
    __shared__ float mu[NG][GS];
    __shared__ float red[NG][152];

    const int g    = threadIdx.x >> 5;
    const int lane = threadIdx.x & 31;
    const float n = (float)NTOT;

    // each lane owns ~5 entries; each entry = 128 contiguous floats = 32 float4
    for (int e = lane; e < 152; e += 32) {
        const float4* p = (const float4*)g_part[g][e];
        float4 s0 = make_float4(0.f, 0.f, 0.f, 0.f), s1 = s0, s2 = s0, s3 = s0;
#pragma unroll
        for (int c = 0; c < NPART / 16; c++) {
            float4 a0 = p[4 * c + 0], a1 = p[4 * c + 1], a2 = p[4 * c + 2], a3 = p[4 * c + 3];
            s0.x += a0.x; s0.y += a0.y; s0.z += a0.z; s0.w += a0.w;
            s1.x += a1.x; s1.y += a1.y; s1.z += a1.z; s1.w += a1.w;
            s2.x += a2.x; s2.y += a2.y; s2.z += a2.z; s2.w += a2.w;
            s3.x += a3.x; s3.y += a3.y; s3.z += a3.z; s3.w += a3.w;
        }
        red[g][e] = ((s0.x + s0.y) + (s0.z + s0.w)) + ((s1.x + s1.y) + (s1.z + s1.w))
                  + ((s2.x + s2.y) + (s2.z + s2.w)) + ((s3.x + s3.y) + (s3.z + s3.w));
    }
    __syncwarp();

    if (lane < GS) mu[g][lane] = red[g][136 + lane] / n;
    __syncwarp();

    for (int idx = lane; idx < 256; idx += 32) {
        const int i = idx >> 4, j = idx & 15;
        const int ii = i > j ? i : j;
        const int jj = i > j ? j : i;
        float G = red[g][ii * (ii + 1) / 2 + jj];
        float sh = (G - n * mu[g][i] * mu[g][j]) / (n - 1.0f);
        a[g][i][j] = (1.0f - 1e-6f) * sh + ((i == j) ? 1e-6f : 0.0f);
    }
    __syncwarp();

    // Cholesky in-place (lower), lane i owns row i
    for (int j = 0; j < GS; j++) {
        if (lane == j) a[g][j][j] = sqrtf(a[g][j][j]);
        __syncwarp();
        const float tjj = a[g][j][j];
        if (lane > j && lane < GS) a[g][lane][j] /= tjj;
        __syncwarp();
        if (lane > j && lane < GS) {
            const float lij = a[g][lane][j];
            for (int k = j + 1; k <= lane; k++)
                a[g][lane][k] -= lij * a[g][k][j];
        }
        __syncwarp();
    }

    // W = T^{-1}: lane j computes column j by forward substitution
    if (lane < GS) {
        const int j = lane;
        w[g][j][j] = 1.0f / a[g][j][j];
        for (int i = j + 1; i < GS; i++) {
            float s = 0.f;
            for (int k = j; k < i; k++) s += a[g][i][k] * w[g][k][j];
            w[g][i][j] = -s / a[g][i][i];
        }
        for (int i = j; i < GS; i++)
            g_W[g][i * (i + 1) / 2 + j] = w[g][i][j];
    }
    __syncwarp();

    if (lane < GS) {
        const int i = lane;
        float b = 0.f;
        for (int j = 0; j <= i; j++) b += w[g][i][j] * mu[g][j];
        g_b[g][i] = b;
    }
}

// ---------------------------------------------------------------------------
// Kernel 3: y = W*x - b (triangular), float4 payload, immediate stores.
// Grid (16,32) = 512 blocks, 128 threads; ~90 live regs (cap 128, no spill);
// 4 blocks/SM -> ALL blocks resident in a single wave (no tail).
// ---------------------------------------------------------------------------
__global__ __launch_bounds__(128, 4) void whiten_kernel(const float* __restrict__ x,
                                                        float* __restrict__ out) {
    const int g = blockIdx.x;
    const int m = blockIdx.y;

    __shared__ float sW[NPAIR];
    __shared__ float sb[GS];
    for (int i = threadIdx.x; i < NPAIR + GS; i += 128) {
        if (i < NPAIR) sW[i] = g_W[g][i];
        else           sb[i - NPAIR] = g_b[g][i - NPAIR];
    }
    __syncthreads();

    const size_t base = ((size_t)m * NF + (size_t)g * GS) * HWS;

    for (int f = threadIdx.x; f < NF4; f += 128) {
        float4 v[GS];
#pragma unroll
        for (int c = 0; c < GS; c++)
            v[c] = ((const float4*)(x + base + (size_t)c * HWS))[f];

#pragma unroll
        for (int i = 0; i < GS; i++) {
            const float b = sb[i];
            float4 y = make_float4(-b, -b, -b, -b);
#pragma unroll
            for (int j = 0; j <= i; j++) {
                const float w = sW[i * (i + 1) / 2 + j];
                y.x = fmaf(w, v[j].x, y.x);
                y.y = fmaf(w, v[j].y, y.y);
                y.z = fmaf(w, v[j].z, y.z);
                y.w = fmaf(w, v[j].w, y.w);
            }
            ((float4*)(out + base + (size_t)i * HWS))[f] = y;
        }
    }
}

// ---------------------------------------------------------------------------
extern "C" void kernel_launch(void* const* d_in, const int* in_sizes, int n_in,
                              void* d_out, int out_size) {
    const float* x = (const float*)d_in[0];
    float* out = (float*)d_out;

    dim3 sgrid(NG, MB, SS);
    stats_kernel<<<sgrid, 320>>>(x);
    solve_kernel<<<1, 512>>>();
    dim3 wgrid(NG, MB);
    whiten_kernel<<<wgrid, 128>>>(x, out);
}

// round 7
// speedup vs baseline: 1.9406x; 1.1959x over previous
#include <cuda_runtime.h>

#define NF  256
#define GS  16
#define NG  16
#define HWS 3136        // 56*56
#define MB  32
#define NTOT (MB*HWS)   // 100352
#define NPAIR 136       // 16*17/2
#define NF2  (HWS/2)    // 1568 float2 positions
#define NF4  (HWS/4)    // 784  float4 positions
#define SS   4          // spatial split (wave smoothing)
#define CH2  (NF2/SS)   // 392 float2 positions per stats chunk
#define CH4  (NF4/SS)   // 196 float4 positions per whiten chunk

typedef unsigned long long u64;

// Scratch (device globals: no allocation allowed)
__device__ float g_sig[NG][152];      // 136 gram pairs + 16 channel sums (atomic)
__device__ float g_W[NG][NPAIR];      // lower-tri inv(chol(Sigma)), k = i*(i+1)/2 + j
__device__ float g_b[NG][GS];         // b_i = sum_{j<=i} W_ij * mu_j

// ---------------------------------------------------------------------------
// packed f32x2 helpers
// ---------------------------------------------------------------------------
__device__ __forceinline__ u64 ffma2(u64 a, u64 b, u64 c) {
    u64 d;
    asm("fma.rn.f32x2 %0, %1, %2, %3;" : "=l"(d) : "l"(a), "l"(b), "l"(c));
    return d;
}
__device__ __forceinline__ float2 u2f2(u64 v) {
    float2 f;
    asm("mov.b64 {%0, %1}, %2;" : "=f"(f.x), "=f"(f.y) : "l"(v));
    return f;
}

// ---------------------------------------------------------------------------
// Kernel 0: zero the atomic accumulators (graph replays must be deterministic)
// ---------------------------------------------------------------------------
__global__ void zero_kernel() {
    for (int i = threadIdx.x; i < NG * 152; i += 256)
        ((float*)g_sig)[i] = 0.f;
}

// ---------------------------------------------------------------------------
// Kernel 1: per-group raw Gram + channel sums, quarter-block decomposition,
// z-split over 4 spatial chunks. Grid (16,32,4), 320 threads = 10 warps.
// Warp epilogue: shfl-reduce then ONE atomicAdd per owned entry. No partial
// buffers, no second-pass reduction.
// ---------------------------------------------------------------------------
template<int QI, int QJ>
__device__ __forceinline__ void qb_warp(const float* __restrict__ base,
                                        int lane, int f0, int g) {
    constexpr bool DIAG = (QI == QJ);
    constexpr int NACC = DIAG ? 10 : 16;

    u64 acc[NACC];
#pragma unroll
    for (int k = 0; k < NACC; k++) acc[k] = 0ull;
    float s[4];
#pragma unroll
    for (int c = 0; c < 4; c++) s[c] = 0.f;

    const int f1 = f0 + CH2;
    for (int f = f0 + lane; f < f1; f += 32) {   // ~12.25 iterations
        u64 va[4];
#pragma unroll
        for (int a = 0; a < 4; a++)
            va[a] = ((const u64*)(base + (size_t)(4 * QI + a) * HWS))[f];
        if (DIAG) {
            int k = 0;
#pragma unroll
            for (int a = 0; a < 4; a++) {
#pragma unroll
                for (int b = 0; b <= a; b++) { acc[k] = ffma2(va[a], va[b], acc[k]); k++; }
                float2 t = u2f2(va[a]);
                s[a] += t.x + t.y;
            }
        } else {
            u64 vb[4];
#pragma unroll
            for (int b = 0; b < 4; b++)
                vb[b] = ((const u64*)(base + (size_t)(4 * QJ + b) * HWS))[f];
#pragma unroll
            for (int a = 0; a < 4; a++)
#pragma unroll
                for (int b = 0; b < 4; b++)
                    acc[a * 4 + b] = ffma2(va[a], vb[b], acc[a * 4 + b]);
        }
    }

    // warp-reduce, then one atomic per entry
    const int DA[10] = {0,1,1,2,2,2,3,3,3,3};
    const int DB[10] = {0,0,1,0,1,2,0,1,2,3};
#pragma unroll
    for (int t = 0; t < NACC; t++) {
        float2 p = u2f2(acc[t]);
        float v = p.x + p.y;
#pragma unroll
        for (int sh = 16; sh > 0; sh >>= 1)
            v += __shfl_xor_sync(0xFFFFFFFFu, v, sh);
        if (lane == 0) {
            const int a = DIAG ? DA[t] : (t >> 2);
            const int b = DIAG ? DB[t] : (t & 3);
            const int i = 4 * QI + a;
            const int j = 4 * QJ + b;
            atomicAdd(&g_sig[g][i * (i + 1) / 2 + j], v);
        }
    }
    if (DIAG) {
#pragma unroll
        for (int c = 0; c < 4; c++) {
            float v = s[c];
#pragma unroll
            for (int sh = 16; sh > 0; sh >>= 1)
                v += __shfl_xor_sync(0xFFFFFFFFu, v, sh);
            if (lane == 0) atomicAdd(&g_sig[g][136 + 4 * QI + c], v);
        }
    }
}

__global__ __launch_bounds__(320, 3) void stats_kernel(const float* __restrict__ x) {
    const int g = blockIdx.x;
    const int m = blockIdx.y;
    const int z = blockIdx.z;
    const float* base = x + ((size_t)m * NF + (size_t)g * GS) * HWS;
    const int wid  = threadIdx.x >> 5;
    const int lane = threadIdx.x & 31;
    const int f0 = z * CH2;
    switch (wid) {
        case 0: qb_warp<0,0>(base, lane, f0, g); break;
        case 1: qb_warp<1,0>(base, lane, f0, g); break;
        case 2: qb_warp<1,1>(base, lane, f0, g); break;
        case 3: qb_warp<2,0>(base, lane, f0, g); break;
        case 4: qb_warp<2,1>(base, lane, f0, g); break;
        case 5: qb_warp<2,2>(base, lane, f0, g); break;
        case 6: qb_warp<3,0>(base, lane, f0, g); break;
        case 7: qb_warp<3,1>(base, lane, f0, g); break;
        case 8: qb_warp<3,2>(base, lane, f0, g); break;
        case 9: qb_warp<3,3>(base, lane, f0, g); break;
    }
}

// ---------------------------------------------------------------------------
// Kernel 2: g_sig -> sigma -> Cholesky -> inverse -> (W, b).
// One warp per group (512 threads), fp32 throughout. Reduction is gone:
// just 152 loads per group.
// ---------------------------------------------------------------------------
__global__ __launch_bounds__(512) void solve_kernel() {
    __shared__ float a [NG][GS][GS + 1];
    __shared__ float w [NG][GS][GS + 1];
    __shared__ float mu[NG][GS];
    __shared__ float red[NG][152];

    const int g    = threadIdx.x >> 5;
    const int lane = threadIdx.x & 31;
    const float n = (float)NTOT;

    for (int e = lane; e < 152; e += 32) red[g][e] = g_sig[g][e];
    __syncwarp();

    if (lane < GS) mu[g][lane] = red[g][136 + lane] / n;
    __syncwarp();

    for (int idx = lane; idx < 256; idx += 32) {
        const int i = idx >> 4, j = idx & 15;
        const int ii = i > j ? i : j;
        const int jj = i > j ? j : i;
        float G = red[g][ii * (ii + 1) / 2 + jj];
        float sh = (G - n * mu[g][i] * mu[g][j]) / (n - 1.0f);
        a[g][i][j] = (1.0f - 1e-6f) * sh + ((i == j) ? 1e-6f : 0.0f);
    }
    __syncwarp();

    // Cholesky in-place (lower), lane i owns row i
    for (int j = 0; j < GS; j++) {
        if (lane == j) a[g][j][j] = sqrtf(a[g][j][j]);
        __syncwarp();
        const float tjj = a[g][j][j];
        if (lane > j && lane < GS) a[g][lane][j] /= tjj;
        __syncwarp();
        if (lane > j && lane < GS) {
            const float lij = a[g][lane][j];
            for (int k = j + 1; k <= lane; k++)
                a[g][lane][k] -= lij * a[g][k][j];
        }
        __syncwarp();
    }

    // W = T^{-1}: lane j computes column j by forward substitution
    if (lane < GS) {
        const int j = lane;
        w[g][j][j] = 1.0f / a[g][j][j];
        for (int i = j + 1; i < GS; i++) {
            float s = 0.f;
            for (int k = j; k < i; k++) s += a[g][i][k] * w[g][k][j];
            w[g][i][j] = -s / a[g][i][i];
        }
        for (int i = j; i < GS; i++)
            g_W[g][i * (i + 1) / 2 + j] = w[g][i][j];
    }
    __syncwarp();

    if (lane < GS) {
        const int i = lane;
        float b = 0.f;
        for (int j = 0; j <= i; j++) b += w[g][i][j] * mu[g][j];
        g_b[g][i] = b;
    }
}

// ---------------------------------------------------------------------------
// Kernel 3: y = W*x - b (triangular), float4, immediate stores, z-split.
// Grid (16,32,4) = 2048 blocks, 128 threads (R3-proven shape).
// ---------------------------------------------------------------------------
__global__ __launch_bounds__(128, 4) void whiten_kernel(const float* __restrict__ x,
                                                        float* __restrict__ out) {
    const int g = blockIdx.x;
    const int m = blockIdx.y;
    const int z = blockIdx.z;

    __shared__ float sW[NPAIR];
    __shared__ float sb[GS];
    for (int i = threadIdx.x; i < NPAIR + GS; i += 128) {
        if (i < NPAIR) sW[i] = g_W[g][i];
        else           sb[i - NPAIR] = g_b[g][i - NPAIR];
    }
    __syncthreads();

    const size_t base = ((size_t)m * NF + (size_t)g * GS) * HWS;
    const int f0 = z * CH4;
    const int f1 = f0 + CH4;

    for (int f = f0 + threadIdx.x; f < f1; f += 128) {
        float4 v[GS];
#pragma unroll
        for (int c = 0; c < GS; c++)
            v[c] = ((const float4*)(x + base + (size_t)c * HWS))[f];

#pragma unroll
        for (int i = 0; i < GS; i++) {
            const float b = sb[i];
            float4 y = make_float4(-b, -b, -b, -b);
#pragma unroll
            for (int j = 0; j <= i; j++) {
                const float w = sW[i * (i + 1) / 2 + j];
                y.x = fmaf(w, v[j].x, y.x);
                y.y = fmaf(w, v[j].y, y.y);
                y.z = fmaf(w, v[j].z, y.z);
                y.w = fmaf(w, v[j].w, y.w);
            }
            ((float4*)(out + base + (size_t)i * HWS))[f] = y;
        }
    }
}

// ---------------------------------------------------------------------------
extern "C" void kernel_launch(void* const* d_in, const int* in_sizes, int n_in,
                              void* d_out, int out_size) {
    const float* x = (const float*)d_in[0];
    float* out = (float*)d_out;

    zero_kernel<<<1, 256>>>();
    dim3 sgrid(NG, MB, SS);
    stats_kernel<<<sgrid, 320>>>(x);
    solve_kernel<<<1, 512>>>();
    dim3 wgrid(NG, MB, SS);
    whiten_kernel<<<wgrid, 128>>>(x, out);
}